// round 6
// baseline (speedup 1.0000x reference)
#include <cuda_runtime.h>
#include <stdint.h>

// ---------------------------------------------------------------------------
// Problem constants
// ---------------------------------------------------------------------------
#define BATCHN 8192
#define EXPD   1024
#define DICTK  4096
#define NITERS 20
#define KSPARSE 409
#define STEPF  0.1f
#define THRF   0.01f   // REG * STEP (f32(0.01) == f32(0.1*0.1 in f64))

// ---------------------------------------------------------------------------
// Theory: reference = XLA f32 matmuls (full fp32, classic SGEMM semantics:
// one fp32 accumulator per output, FFMA chain ascending in k). We reproduce
// that bit-for-bit: fp32 operands straight from memory, ascending-k FFMA,
// fp32 state. No precision tricks anywhere.
// ---------------------------------------------------------------------------
__device__ __align__(16) float g_DT [EXPD * DICTK];              // D^T fp32
__device__ __align__(16) float g_r  [(size_t)BATCHN * EXPD];     // residual fp32
__device__ __align__(16) float g_astate[(size_t)BATCHN * DICTK]; // alpha fp32

// ---------------------------------------------------------------------------
// Helpers
// ---------------------------------------------------------------------------
__device__ __forceinline__ void cp_async16(void* smem, const void* gmem) {
    unsigned s = (unsigned)__cvta_generic_to_shared(smem);
    asm volatile("cp.async.cg.shared.global [%0], [%1], 16;" :: "r"(s), "l"(gmem));
}
__device__ __forceinline__ void cp_commit() {
    asm volatile("cp.async.commit_group;" ::: "memory");
}
__device__ __forceinline__ void cp_wait1() {
    asm volatile("cp.async.wait_group 1;" ::: "memory");
}
__device__ __forceinline__ void cp_wait0() {
    asm volatile("cp.async.wait_group 0;" ::: "memory");
}

// ---------------------------------------------------------------------------
// D[4096,1024] -> DT[1024,4096] (fp32 transpose)
// ---------------------------------------------------------------------------
__global__ void __launch_bounds__(1024) transpose_kernel(
    const float* __restrict__ D, float* __restrict__ DT)
{
    __shared__ float tile[32][33];
    int tx = threadIdx.x, ty = threadIdx.y;
    int c = blockIdx.x * 32 + tx;   // col in D (0..1023)
    int r = blockIdx.y * 32 + ty;   // row in D (0..4095)
    tile[ty][tx] = D[(size_t)r * EXPD + c];
    __syncthreads();
    int orow = blockIdx.x * 32 + ty;  // row of DT
    int ocol = blockIdx.y * 32 + tx;  // col of DT
    DT[(size_t)orow * DICTK + ocol] = tile[tx][ty];
}

// ---------------------------------------------------------------------------
// fp32 SIMT GEMM: C[128x128] per CTA, 256 threads, 8x8 microtile, k-tile 16.
// Accumulation: strictly ascending k, single fp32 accumulator per output ->
// classic SGEMM bit-semantics.
// EPI==1 : Rout = Xp - C
// EPI==2 : a = Astate + STEP*C (fmaf); soft-threshold; Astate = a
// ---------------------------------------------------------------------------
#define AP 20     // A smem pitch (floats), layout [m][k]
#define BP 132    // B smem pitch (floats), layout [k][n]

template<int EPI, bool ZERO_ALPHA>
__global__ void __launch_bounds__(256) gemm_f32(
    const float* __restrict__ A, const float* __restrict__ B,
    int Kin, int Nfull,
    const float* __restrict__ Xp,      // EPI1
    float* __restrict__ Rout,          // EPI1
    float* __restrict__ Astate)        // EPI2 (in/out)
{
    __shared__ float As[2][128 * AP];
    __shared__ float Bs[2][16 * BP];

    const int tid = threadIdx.x;
    const int tx = tid & 15;          // n-direction (8 cols each)
    const int ty = tid >> 4;          // m-direction (8 rows each)
    const int bm = blockIdx.y * 128;
    const int bn = blockIdx.x * 128;
    const int ktiles = Kin >> 4;

    float acc[8][8];
#pragma unroll
    for (int r = 0; r < 8; r++)
#pragma unroll
        for (int c = 0; c < 8; c++) acc[r][c] = 0.f;

    auto issue = [&](int t, int buf) {
        int kk = t << 4;
#pragma unroll
        for (int i = 0; i < 2; i++) {         // A tile: 128 rows x 16 k = 512 x 16B
            int c = tid + (i << 8);
            int row = c >> 2, kq = (c & 3) << 2;
            cp_async16(&As[buf][row * AP + kq],
                       A + (size_t)(bm + row) * Kin + kk + kq);
        }
#pragma unroll
        for (int i = 0; i < 2; i++) {         // B tile: 16 k x 128 n = 512 x 16B
            int c = tid + (i << 8);
            int kr = c >> 5, nq = (c & 31) << 2;
            cp_async16(&Bs[buf][kr * BP + nq],
                       B + (size_t)(kk + kr) * Nfull + bn + nq);
        }
        cp_commit();
    };

    issue(0, 0);
    for (int t = 0; t < ktiles; t++) {
        if (t + 1 < ktiles) { issue(t + 1, (t + 1) & 1); cp_wait1(); }
        else                { cp_wait0(); }
        __syncthreads();

        const float* Ab = As[t & 1];
        const float* Bb = Bs[t & 1];
#pragma unroll
        for (int k = 0; k < 16; k++) {        // ascending k within tile
            float a[8];
#pragma unroll
            for (int r = 0; r < 8; r++)
                a[r] = Ab[(ty * 8 + r) * AP + k];
            float4 b0 = *reinterpret_cast<const float4*>(&Bb[k * BP + tx * 8]);
            float4 b1 = *reinterpret_cast<const float4*>(&Bb[k * BP + tx * 8 + 4]);
            float b[8] = {b0.x, b0.y, b0.z, b0.w, b1.x, b1.y, b1.z, b1.w};
#pragma unroll
            for (int r = 0; r < 8; r++)
#pragma unroll
                for (int c = 0; c < 8; c++)
                    acc[r][c] = __fmaf_rn(a[r], b[c], acc[r][c]);
        }
        __syncthreads();
    }

    // ---------------- epilogue ----------------
#pragma unroll
    for (int r = 0; r < 8; r++) {
        int m = bm + ty * 8 + r;
#pragma unroll
        for (int c4 = 0; c4 < 2; c4++) {
            int n = bn + tx * 8 + c4 * 4;
            size_t idx = (size_t)m * Nfull + n;
            if (EPI == 1) {
                float4 x4 = *reinterpret_cast<const float4*>(Xp + idx);
                float4 o;
                o.x = x4.x - acc[r][c4 * 4 + 0];
                o.y = x4.y - acc[r][c4 * 4 + 1];
                o.z = x4.z - acc[r][c4 * 4 + 2];
                o.w = x4.w - acc[r][c4 * 4 + 3];
                *reinterpret_cast<float4*>(Rout + idx) = o;
            } else {
                float4 st;
                if (ZERO_ALPHA) { st.x = st.y = st.z = st.w = 0.f; }
                else st = *reinterpret_cast<const float4*>(Astate + idx);
                float v[4];
                v[0] = __fmaf_rn(STEPF, acc[r][c4 * 4 + 0], st.x);
                v[1] = __fmaf_rn(STEPF, acc[r][c4 * 4 + 1], st.y);
                v[2] = __fmaf_rn(STEPF, acc[r][c4 * 4 + 2], st.z);
                v[3] = __fmaf_rn(STEPF, acc[r][c4 * 4 + 3], st.w);
                float4 o;
                float* op = &o.x;
#pragma unroll
                for (int q = 0; q < 4; q++) {
                    float mm = fabsf(v[q]) - THRF;
                    op[q] = (mm > 0.f) ? copysignf(mm, v[q]) : 0.f;
                }
                *reinterpret_cast<float4*>(Astate + idx) = o;
            }
        }
    }
}

// ---------------------------------------------------------------------------
// Per-row top-409 by |alpha| (exact radix select; index-ordered ties, matching
// jax.lax.top_k). One CTA (256 thr) per row. Reads fp32 alpha state.
// ---------------------------------------------------------------------------
__global__ void __launch_bounds__(256) topk_kernel(
    const float* __restrict__ astate, float* __restrict__ out)
{
    __shared__ float vals[DICTK];
    __shared__ int hist[256];
    __shared__ int tcnt[256];
    __shared__ unsigned sh_prefix;
    __shared__ int sh_krem;

    const int row = blockIdx.x;
    const int tid = threadIdx.x;
    const size_t base = (size_t)row * DICTK;

    for (int j = tid; j < DICTK / 4; j += 256) {
        float4 v4 = *reinterpret_cast<const float4*>(astate + base + j * 4);
        *reinterpret_cast<float4*>(vals + j * 4) = v4;
    }
    if (tid == 0) { sh_prefix = 0u; sh_krem = KSPARSE; }
    __syncthreads();

    for (int pass = 0; pass < 4; pass++) {
        int shift = 24 - 8 * pass;
        hist[tid] = 0;
        __syncthreads();
        unsigned pref = sh_prefix;
        unsigned maskk = (pass == 0) ? 0u : (0xFFFFFFFFu << (shift + 8));
        for (int j = tid; j < DICTK; j += 256) {
            unsigned key = __float_as_uint(fabsf(vals[j]));
            if ((key & maskk) == pref) atomicAdd(&hist[(key >> shift) & 255], 1);
        }
        __syncthreads();
        if (tid == 0) {
            int krem = sh_krem, cum = 0, b = 255;
            for (; b > 0; b--) {
                if (cum + hist[b] >= krem) break;
                cum += hist[b];
            }
            sh_prefix = pref | ((unsigned)b << shift);
            sh_krem = krem - cum;
        }
        __syncthreads();
    }
    const unsigned T = sh_prefix;
    const int krem = sh_krem;

    // index-ordered rank among elements with key == T
    const int c0 = tid * 16;
    int cnt = 0;
    for (int j = c0; j < c0 + 16; j++)
        if (__float_as_uint(fabsf(vals[j])) == T) cnt++;
    tcnt[tid] = cnt;
    __syncthreads();
    if (tid == 0) {
        int run = 0;
        for (int i = 0; i < 256; i++) { int c = tcnt[i]; tcnt[i] = run; run += c; }
    }
    __syncthreads();

    int rank = tcnt[tid];
    for (int j4 = 0; j4 < 4; j4++) {
        float4 o;
        float* op = &o.x;
#pragma unroll
        for (int q = 0; q < 4; q++) {
            int j = c0 + j4 * 4 + q;
            float v = vals[j];
            unsigned key = __float_as_uint(fabsf(v));
            float ov;
            if (key > T) ov = v;
            else if (key == T) { ov = (rank < krem) ? v : 0.f; rank++; }
            else ov = 0.f;
            op[q] = ov;
        }
        *reinterpret_cast<float4*>(out + base + c0 + j4 * 4) = o;
    }
}

// ---------------------------------------------------------------------------
// Host driver
// ---------------------------------------------------------------------------
extern "C" void kernel_launch(void* const* d_in, const int* in_sizes, int n_in,
                              void* d_out, int out_size)
{
    const float* X = (const float*)d_in[0];
    const float* D = (const float*)d_in[1];
    if (n_in >= 2 && in_sizes[0] == DICTK * EXPD) {   // order sniff via sizes
        D = (const float*)d_in[0];
        X = (const float*)d_in[1];
    }
    float* out = (float*)d_out;

    void *pDT, *pR, *pAst;
    cudaGetSymbolAddress(&pDT, g_DT);
    cudaGetSymbolAddress(&pR, g_r);
    cudaGetSymbolAddress(&pAst, g_astate);
    float* DT  = (float*)pDT;
    float* R   = (float*)pR;
    float* Ast = (float*)pAst;

    // 1) transpose dictionary
    transpose_kernel<<<dim3(EXPD / 32, DICTK / 32), dim3(32, 32)>>>(D, DT);

    // 2) iter 0: alpha=0 -> residual = X; alpha1 = shrink(0.1 * X @ D^T)
    gemm_f32<2, true><<<dim3(DICTK / 128, BATCHN / 128), 256>>>(
        X, DT, EXPD, DICTK, nullptr, nullptr, Ast);

    // 3) iters 1..19
    for (int it = 1; it < NITERS; ++it) {
        gemm_f32<1, false><<<dim3(EXPD / 128, BATCHN / 128), 256>>>(
            Ast, D, DICTK, EXPD, X, R, nullptr);
        gemm_f32<2, false><<<dim3(DICTK / 128, BATCHN / 128), 256>>>(
            R, DT, EXPD, DICTK, nullptr, nullptr, Ast);
    }

    // 4) per-row hard top-k on fp32 alpha state
    topk_kernel<<<BATCHN, 256>>>(Ast, out);
    (void)out_size;
}